// round 1
// baseline (speedup 1.0000x reference)
#include <cuda_runtime.h>

#define EPS_F 1e-9f
#define MAX_NODES 200000
#define DIM 128

// Scratch (no allocations allowed): compact per-node table + accumulators.
__device__ float2 g_tab[MAX_NODES];
__device__ double g_acc[2];   // [0] = proximity sum, [1] = compactness sum

// ---------------------------------------------------------------------------
// helpers
// ---------------------------------------------------------------------------
__device__ __forceinline__ double block_reduce_double(double v) {
    __shared__ double s[32];
    int lane = threadIdx.x & 31;
    int wid  = threadIdx.x >> 5;
    #pragma unroll
    for (int o = 16; o; o >>= 1) v += __shfl_down_sync(0xffffffffu, v, o);
    if (lane == 0) s[wid] = v;
    __syncthreads();
    int nwarps = (blockDim.x + 31) >> 5;
    v = (threadIdx.x < (unsigned)nwarps) ? s[threadIdx.x] : 0.0;
    if (wid == 0) {
        #pragma unroll
        for (int o = 16; o; o >>= 1) v += __shfl_down_sync(0xffffffffu, v, o);
    }
    return v;
}

__device__ __forceinline__ float safe_div(float num, float den) {
    float sgn  = (den > 0.0f) ? 1.0f : ((den < 0.0f) ? -1.0f : 0.0f);
    float safe = fmaxf(fabsf(den), EPS_F) * sgn;
    return num / safe;
}

// quadrance for a point pair given compact (x,y); aa = 1 - x^2 - y^2
__device__ __forceinline__ float edge_quad(float2 a, float2 b) {
    float aa = 1.0f - (a.x * a.x + a.y * a.y);
    float bb = 1.0f - (b.x * b.x + b.y * b.y);
    float ab = 1.0f - (a.x * b.x + a.y * b.y);
    float den = aa * bb;
    float num = ab * ab - den;
    return safe_div(num, den);
}

// ---------------------------------------------------------------------------
// kernels
// ---------------------------------------------------------------------------
__global__ void init_kernel() {
    g_acc[0] = 0.0;
    g_acc[1] = 0.0;
}

// Build compact (x,y) table + compactness sum.
__global__ void node_kernel(const float* __restrict__ z, int n_nodes) {
    int i = blockIdx.x * blockDim.x + threadIdx.x;
    double comp = 0.0;
    if (i < n_nodes) {
        float2 xy = *reinterpret_cast<const float2*>(z + (size_t)i * DIM);
        g_tab[i] = xy;
        // quad(point, origin): aa = 1 - x^2 - y^2, bb = 1, ab = 1
        float aa  = 1.0f - (xy.x * xy.x + xy.y * xy.y);
        float num = 1.0f - aa;   // ab*ab - aa*bb
        comp = (double)safe_div(num, aa);
    }
    double bsum = block_reduce_double(comp);
    if (threadIdx.x == 0) atomicAdd(&g_acc[1], bsum);
}

// Proximity over all edges: streaming index reads + random table gathers.
__global__ void edge_kernel(const int* __restrict__ src,
                            const int* __restrict__ dst,
                            long long n_edges) {
    long long tid    = (long long)blockIdx.x * blockDim.x + threadIdx.x;
    long long stride = (long long)gridDim.x * blockDim.x;
    double acc = 0.0;

    long long n4 = n_edges >> 2;
    const int4* s4 = reinterpret_cast<const int4*>(src);
    const int4* d4 = reinterpret_cast<const int4*>(dst);
    for (long long i = tid; i < n4; i += stride) {
        int4 s = s4[i];
        int4 d = d4[i];
        float2 a0 = g_tab[s.x], b0 = g_tab[d.x];
        float2 a1 = g_tab[s.y], b1 = g_tab[d.y];
        float2 a2 = g_tab[s.z], b2 = g_tab[d.z];
        float2 a3 = g_tab[s.w], b3 = g_tab[d.w];
        acc += (double)edge_quad(a0, b0);
        acc += (double)edge_quad(a1, b1);
        acc += (double)edge_quad(a2, b2);
        acc += (double)edge_quad(a3, b3);
    }
    // tail (E not divisible by 4)
    for (long long e = (n4 << 2) + tid; e < n_edges; e += stride) {
        acc += (double)edge_quad(g_tab[src[e]], g_tab[dst[e]]);
    }

    double bsum = block_reduce_double(acc);
    if (threadIdx.x == 0) atomicAdd(&g_acc[0], bsum);
}

// Spread over first min(10, E) edges + final combine. One warp.
__global__ void final_kernel(const int* __restrict__ src,
                             const int* __restrict__ dst,
                             long long n_edges, int n_nodes, int n_sp,
                             float* __restrict__ out) {
    int lane = threadIdx.x;
    double q = 0.0;
    if (lane < n_sp) {
        int s = src[lane], d = dst[lane];
        float2 a = g_tab[s], b = g_tab[d];
        // lines: cross([x,y,1],[0,0,1]) = (y, -x, 0); time component is 0
        float aa = -(a.y * a.y + a.x * a.x);
        float bb = -(b.y * b.y + b.x * b.x);
        float ab = -(a.y * b.y + a.x * b.x);
        float den = aa * bb;
        float num = ab * ab - den;
        q = (double)safe_div(num, den);
    }
    #pragma unroll
    for (int o = 16; o; o >>= 1) q += __shfl_down_sync(0xffffffffu, q, o);
    if (lane == 0) {
        double prox   = g_acc[0] / (double)n_edges;
        double comp   = g_acc[1] / (double)n_nodes;
        double spread = q / (double)n_sp;
        out[0] = (float)(1.0 * (prox + comp) + 0.1 * spread);
    }
}

// ---------------------------------------------------------------------------
// launch
// ---------------------------------------------------------------------------
extern "C" void kernel_launch(void* const* d_in, const int* in_sizes, int n_in,
                              void* d_out, int out_size) {
    const float* z  = (const float*)d_in[0];
    const int*   ei = (const int*)d_in[1];

    int       n_nodes = in_sizes[0] / DIM;
    long long n_edges = (long long)in_sizes[1] / 2;
    const int* src = ei;
    const int* dst = ei + n_edges;

    init_kernel<<<1, 1>>>();

    int nb_node = (n_nodes + 255) / 256;
    node_kernel<<<nb_node, 256>>>(z, n_nodes);

    // ~8 blocks per SM (148 SMs) of 256 threads; grid-stride covers 12.8M edges.
    edge_kernel<<<1184, 256>>>(src, dst, n_edges);

    int n_sp = (int)((n_edges < 10) ? n_edges : 10);
    final_kernel<<<1, 32>>>(src, dst, n_edges, n_nodes, n_sp, (float*)d_out);
}